// round 1
// baseline (speedup 1.0000x reference)
#include <cuda_runtime.h>

#define BATCH 65536
#define AR 16
#define UD 15
#define SEQ 1024
#define ROWS17 17
#define BT 128
#define TT 128

// Scratch (allocation-free rule: __device__ globals)
__device__ float g_A[SEQ * ROWS17];     // t-major: g_A[t*17 + i]
__device__ float g_const[BATCH];

// ---------------------------------------------------------------------------
// Setup kernel:
//   block 0, lanes 0..16: build A via transposed direct-form-II AR(16) recursion.
//     Row i<16:  impulse response with initial window e_i  (A[i,t]=delta(i,t), t<16)
//     Row 16:    constant-injection response c[t] (c=0 for t<16, c_t = 1 + sum w_j c_{t-16+j})
//   blocks 1..256: const[b] = u[b] @ w[16:31] + w[31]
// ---------------------------------------------------------------------------
__global__ void arx_setup_kernel(const float* __restrict__ y,
                                 const float* __restrict__ u,
                                 const float* __restrict__ w) {
    if (blockIdx.x == 0) {
        int i = threadIdx.x;
        if (i < ROWS17) {
            float wr[16];
#pragma unroll
            for (int j = 0; j < 16; ++j) wr[j] = w[j];

            // transposed-form states: s[j] == s_{j+1};  y_t = s[0] + inp
            // s[j] <- s[j+1] + w[15-j]*y_t ;  s[15] <- w[0]*y_t
            float s[16];
#pragma unroll
            for (int j = 0; j < 16; ++j)
                s[j] = (i < 16 && j <= i) ? wr[i - j] : 0.0f;
            float inp = (i == 16) ? 1.0f : 0.0f;

#pragma unroll
            for (int t = 0; t < 16; ++t)
                g_A[t * ROWS17 + i] = (t == i) ? 1.0f : 0.0f;

#pragma unroll 4
            for (int t = 16; t < SEQ; ++t) {
                float yv = s[0] + inp;
                g_A[t * ROWS17 + i] = yv;
#pragma unroll
                for (int j = 0; j < 15; ++j)
                    s[j] = fmaf(wr[15 - j], yv, s[j + 1]);
                s[15] = wr[0] * yv;
            }
        }
    } else {
        int gid = (blockIdx.x - 1) * blockDim.x + threadIdx.x;
        if (gid < BATCH) {
            const float* ur = u + (size_t)gid * UD;
            float acc = w[16 + UD];          // bias w[31]
#pragma unroll
            for (int j = 0; j < UD; ++j)
                acc = fmaf(ur[j], w[16 + j], acc);
            g_const[gid] = acc;
        }
    }
}

// ---------------------------------------------------------------------------
// Main kernel: out[b,t] = sum_{i<16} y[b,i]*A[i,t] + const[b]*A[16,t]
// Block: 128 batch rows x 128 t. Thread: 4 rows x 16 t, f32x2-packed along t.
// ---------------------------------------------------------------------------
__device__ __forceinline__ unsigned long long ffma2(unsigned long long a,
                                                    unsigned long long b,
                                                    unsigned long long c) {
    unsigned long long d;
    asm("fma.rn.f32x2 %0, %1, %2, %3;" : "=l"(d) : "l"(a), "l"(b), "l"(c));
    return d;
}

union F2U { unsigned long long u; float2 f; };

__global__ void __launch_bounds__(256, 2)
arx_main_kernel(const float* __restrict__ y, float* __restrict__ out) {
    __shared__ float2 sy2[ROWS17][BT];        // duplicated-packed (v,v)
    __shared__ float  sA[ROWS17][TT + 4];     // row stride 132 floats (16B aligned)

    const int tid = threadIdx.x;
    const int bx  = blockIdx.x;
    const int t0  = (bx & 7) * TT;            // 8 t-chunks
    const int b0  = (bx >> 3) * BT;           // 512 batch groups

    // stage y + const, duplicated into f32x2 lanes
    for (int idx = tid; idx < ROWS17 * BT; idx += 256) {
        int r = idx / ROWS17;
        int i = idx - r * ROWS17;
        float v = (i < AR) ? y[(size_t)(b0 + r) * AR + i] : g_const[b0 + r];
        sy2[i][r] = make_float2(v, v);
    }
    // stage A chunk (coalesced: g_A is t-major)
    for (int idx = tid; idx < ROWS17 * TT; idx += 256) {
        int tt = idx / ROWS17;
        int i  = idx - tt * ROWS17;
        sA[i][tt] = g_A[(size_t)(t0 + tt) * ROWS17 + i];
    }
    __syncthreads();

    const int tx = tid & 7;    // t-group: 16 consecutive t per thread
    const int ty = tid >> 3;   // 32 row-slots; rows = rr*32 + ty

    unsigned long long acc[4][8];
#pragma unroll
    for (int rr = 0; rr < 4; ++rr)
#pragma unroll
        for (int p = 0; p < 8; ++p) acc[rr][p] = 0ull;

#pragma unroll
    for (int i = 0; i < ROWS17; ++i) {
        unsigned long long ys[4];
#pragma unroll
        for (int rr = 0; rr < 4; ++rr)
            ys[rr] = *reinterpret_cast<const unsigned long long*>(&sy2[i][rr * 32 + ty]);

        const ulonglong2* ap =
            reinterpret_cast<const ulonglong2*>(&sA[i][tx * 16]);
#pragma unroll
        for (int q = 0; q < 4; ++q) {
            ulonglong2 a2 = ap[q];   // 4 floats = 2 packed f32x2 (t, t+1)
#pragma unroll
            for (int rr = 0; rr < 4; ++rr) {
                acc[rr][2 * q]     = ffma2(ys[rr], a2.x, acc[rr][2 * q]);
                acc[rr][2 * q + 1] = ffma2(ys[rr], a2.y, acc[rr][2 * q + 1]);
            }
        }
    }

    // coalesced float4 epilogue: lanes tx=0..7 cover 128B contiguous per row
#pragma unroll
    for (int rr = 0; rr < 4; ++rr) {
        int row = b0 + rr * 32 + ty;
        float4* op = reinterpret_cast<float4*>(out + (size_t)row * SEQ + t0 + tx * 16);
#pragma unroll
        for (int q = 0; q < 4; ++q) {
            F2U lo, hi;
            lo.u = acc[rr][2 * q];
            hi.u = acc[rr][2 * q + 1];
            op[q] = make_float4(lo.f.x, lo.f.y, hi.f.x, hi.f.y);
        }
    }
}

extern "C" void kernel_launch(void* const* d_in, const int* in_sizes, int n_in,
                              void* d_out, int out_size) {
    const float* y = (const float*)d_in[0];   // [65536,16]
    const float* u = (const float*)d_in[1];   // [65536,15]
    const float* w = (const float*)d_in[2];   // [32]
    float* out = (float*)d_out;               // [65536,1024]

    arx_setup_kernel<<<1 + BATCH / 256, 256>>>(y, u, w);
    arx_main_kernel<<<(BATCH / BT) * (SEQ / TT), 256>>>(y, out);
}

// round 2
// speedup vs baseline: 1.9914x; 1.9914x over previous
#include <cuda_runtime.h>

#define BATCH 65536
#define AR 16
#define UD 15
#define SEQ 1024
#define ROWS17 17
#define BT_ROWS 32
#define BT_T 128

// Scratch (allocation-free rule: __device__ globals)
__device__ float g_A[ROWS17 * SEQ];     // i-major: g_A[i*SEQ + t]
__device__ float g_const[BATCH];

// ---------------------------------------------------------------------------
// Setup kernel:
//   block 0, lanes 0..16: build A via transposed direct-form AR(16) recursion.
//   blocks 1..256: const[b] = u[b] @ w[16:31] + w[31]
// ---------------------------------------------------------------------------
__global__ void arx_setup_kernel(const float* __restrict__ y,
                                 const float* __restrict__ u,
                                 const float* __restrict__ w) {
    if (blockIdx.x == 0) {
        int i = threadIdx.x;
        if (i < ROWS17) {
            float wr[16];
#pragma unroll
            for (int j = 0; j < 16; ++j) wr[j] = w[j];

            float s[16];
#pragma unroll
            for (int j = 0; j < 16; ++j)
                s[j] = (i < 16 && j <= i) ? wr[i - j] : 0.0f;
            float inp = (i == 16) ? 1.0f : 0.0f;

#pragma unroll
            for (int t = 0; t < 16; ++t)
                g_A[i * SEQ + t] = (t == i) ? 1.0f : 0.0f;

#pragma unroll 4
            for (int t = 16; t < SEQ; ++t) {
                float yv = s[0] + inp;
                g_A[i * SEQ + t] = yv;
#pragma unroll
                for (int j = 0; j < 15; ++j)
                    s[j] = fmaf(wr[15 - j], yv, s[j + 1]);
                s[15] = wr[0] * yv;
            }
        }
    } else {
        int gid = (blockIdx.x - 1) * blockDim.x + threadIdx.x;
        if (gid < BATCH) {
            const float* ur = u + (size_t)gid * UD;
            float acc = w[16 + UD];          // bias w[31]
#pragma unroll
            for (int j = 0; j < UD; ++j)
                acc = fmaf(ur[j], w[16 + j], acc);
            g_const[gid] = acc;
        }
    }
}

// ---------------------------------------------------------------------------
// Main kernel: out[b,t] = sum_{i<16} y[b,i]*A[i,t] + const[b]*A[16,t]
// Warp tile: 4 rows x 128 t (lanes cover t). Thread: 4 rows x 4 t.
// f32x2 packs ROW PAIRS; A is scalar-broadcast, dup'd in regs.
// ---------------------------------------------------------------------------
__device__ __forceinline__ unsigned long long ffma2(unsigned long long a,
                                                    unsigned long long b,
                                                    unsigned long long c) {
    unsigned long long d;
    asm("fma.rn.f32x2 %0, %1, %2, %3;" : "=l"(d) : "l"(a), "l"(b), "l"(c));
    return d;
}

__device__ __forceinline__ unsigned long long pack2(float lo, float hi) {
    unsigned long long d;
    asm("mov.b64 %0, {%1, %2};" : "=l"(d) : "f"(lo), "f"(hi));
    return d;
}

__device__ __forceinline__ unsigned long long dup2(float v) {
    unsigned long long d;
    asm("mov.b64 %0, {%1, %1};" : "=l"(d) : "f"(v));
    return d;
}

union F2U { unsigned long long u; float2 f; };

__global__ void __launch_bounds__(256, 2)
arx_main_kernel(const float* __restrict__ y, float* __restrict__ out) {
    __shared__ float sA[ROWS17][BT_T];   // 8.5 KB, scalar A chunk

    const int tid  = threadIdx.x;
    const int bx   = blockIdx.x;
    const int t0   = (bx & 7) * BT_T;          // 8 t-chunks of 128
    const int r0   = (bx >> 3) * BT_ROWS;      // 2048 row blocks of 32

    // stage A chunk: coalesced (consecutive tid -> consecutive t)
#pragma unroll
    for (int k = 0; k < (ROWS17 * BT_T + 255) / 256; ++k) {
        int idx = tid + k * 256;
        if (idx < ROWS17 * BT_T) {
            int i  = idx >> 7;
            int tt = idx & (BT_T - 1);
            sA[i][tt] = g_A[i * SEQ + t0 + tt];
        }
    }

    const int wid  = tid >> 5;
    const int lane = tid & 31;
    const int rowbase = r0 + wid * 4;          // warp owns 4 rows

    // y (+const) into packed row-pair registers: 2*17 packs = 68 regs
    unsigned long long ypk01[ROWS17], ypk23[ROWS17];
    {
        const float* y0 = y + (size_t)(rowbase + 0) * AR;
        const float* y1 = y + (size_t)(rowbase + 1) * AR;
        const float* y2 = y + (size_t)(rowbase + 2) * AR;
        const float* y3 = y + (size_t)(rowbase + 3) * AR;
#pragma unroll
        for (int i = 0; i < AR; ++i) {
            ypk01[i] = pack2(y0[i], y1[i]);
            ypk23[i] = pack2(y2[i], y3[i]);
        }
        ypk01[16] = pack2(g_const[rowbase + 0], g_const[rowbase + 1]);
        ypk23[16] = pack2(g_const[rowbase + 2], g_const[rowbase + 3]);
    }
    __syncthreads();

    unsigned long long acc01[4] = {0ull, 0ull, 0ull, 0ull};
    unsigned long long acc23[4] = {0ull, 0ull, 0ull, 0ull};

#pragma unroll
    for (int i = 0; i < ROWS17; ++i) {
        // conflict-free: lanes read consecutive 16B chunks
        float4 a4 = *reinterpret_cast<const float4*>(&sA[i][lane * 4]);
        unsigned long long ad0 = dup2(a4.x);
        unsigned long long ad1 = dup2(a4.y);
        unsigned long long ad2 = dup2(a4.z);
        unsigned long long ad3 = dup2(a4.w);
        acc01[0] = ffma2(ypk01[i], ad0, acc01[0]);
        acc23[0] = ffma2(ypk23[i], ad0, acc23[0]);
        acc01[1] = ffma2(ypk01[i], ad1, acc01[1]);
        acc23[1] = ffma2(ypk23[i], ad1, acc23[1]);
        acc01[2] = ffma2(ypk01[i], ad2, acc01[2]);
        acc23[2] = ffma2(ypk23[i], ad2, acc23[2]);
        acc01[3] = ffma2(ypk01[i], ad3, acc01[3]);
        acc23[3] = ffma2(ypk23[i], ad3, acc23[3]);
    }

    // epilogue: unpack row-pairs, coalesced float4 stores per row
    F2U a0, a1, a2, a3;
    const size_t tcol = (size_t)t0 + lane * 4;
    {
        a0.u = acc01[0]; a1.u = acc01[1]; a2.u = acc01[2]; a3.u = acc01[3];
        *reinterpret_cast<float4*>(out + (size_t)(rowbase + 0) * SEQ + tcol) =
            make_float4(a0.f.x, a1.f.x, a2.f.x, a3.f.x);
        *reinterpret_cast<float4*>(out + (size_t)(rowbase + 1) * SEQ + tcol) =
            make_float4(a0.f.y, a1.f.y, a2.f.y, a3.f.y);
    }
    {
        a0.u = acc23[0]; a1.u = acc23[1]; a2.u = acc23[2]; a3.u = acc23[3];
        *reinterpret_cast<float4*>(out + (size_t)(rowbase + 2) * SEQ + tcol) =
            make_float4(a0.f.x, a1.f.x, a2.f.x, a3.f.x);
        *reinterpret_cast<float4*>(out + (size_t)(rowbase + 3) * SEQ + tcol) =
            make_float4(a0.f.y, a1.f.y, a2.f.y, a3.f.y);
    }
}

extern "C" void kernel_launch(void* const* d_in, const int* in_sizes, int n_in,
                              void* d_out, int out_size) {
    const float* y = (const float*)d_in[0];   // [65536,16]
    const float* u = (const float*)d_in[1];   // [65536,15]
    const float* w = (const float*)d_in[2];   // [32]
    float* out = (float*)d_out;               // [65536,1024]

    arx_setup_kernel<<<1 + BATCH / 256, 256>>>(y, u, w);
    // grid: 2048 row-blocks * 8 t-chunks
    arx_main_kernel<<<(BATCH / BT_ROWS) * (SEQ / BT_T), 256>>>(y, out);
}

// round 4
// speedup vs baseline: 3.0237x; 1.5184x over previous
#include <cuda_runtime.h>

#define BATCH 65536
#define AR 16
#define UD 15
#define SEQ 1024
#define ROWS17 17
#define ROWS_PB 64

// Scratch (allocation-free rule: __device__ global)
__device__ float g_A[ROWS17 * SEQ];     // i-major: g_A[i*SEQ + t]

// ---------------------------------------------------------------------------
// Setup kernel: 1 block, lanes 0..16 build A via transposed direct-form AR(16).
//   Row i<16:  response to initial window e_i
//   Row 16:    constant-injection response
// ---------------------------------------------------------------------------
__global__ void arx_setup_kernel(const float* __restrict__ w) {
    int i = threadIdx.x;
    if (i < ROWS17) {
        float wr[16];
#pragma unroll
        for (int j = 0; j < 16; ++j) wr[j] = w[j];

        float s[16];
#pragma unroll
        for (int j = 0; j < 16; ++j)
            s[j] = (i < 16 && j <= i) ? wr[i - j] : 0.0f;
        float inp = (i == 16) ? 1.0f : 0.0f;

#pragma unroll
        for (int t = 0; t < 16; ++t)
            g_A[i * SEQ + t] = (t == i) ? 1.0f : 0.0f;

#pragma unroll 4
        for (int t = 16; t < SEQ; ++t) {
            float yv = s[0] + inp;
            g_A[i * SEQ + t] = yv;
#pragma unroll
            for (int j = 0; j < 15; ++j)
                s[j] = fmaf(wr[15 - j], yv, s[j + 1]);
            s[15] = wr[0] * yv;
        }
    }
}

// ---------------------------------------------------------------------------
// Main kernel: out[b,t] = sum_{i<17} y_ext[b,i]*A[i,t]
// Warp owns a fixed 128-t slice (lane = 4 consecutive t); A packs in regs.
// Rows streamed from smem holding y pre-duplicated (v,v): one LDS.128
// broadcast yields the f32x2 dups for two i's with zero MOVs.
// ---------------------------------------------------------------------------
__device__ __forceinline__ unsigned long long ffma2(unsigned long long a,
                                                    unsigned long long b,
                                                    unsigned long long c) {
    unsigned long long d;
    asm("fma.rn.f32x2 %0, %1, %2, %3;" : "=l"(d) : "l"(a), "l"(b), "l"(c));
    return d;
}

__device__ __forceinline__ unsigned long long pack2(float lo, float hi) {
    unsigned long long d;
    asm("mov.b64 %0, {%1, %2};" : "=l"(d) : "f"(lo), "f"(hi));
    return d;
}

union F2U { unsigned long long u; float2 f; };

__global__ void __launch_bounds__(256, 2)
arx_main_kernel(const float* __restrict__ y, const float* __restrict__ u,
                const float* __restrict__ w, float* __restrict__ out) {
    // pre-duplicated y (+const): sy[r][i] = (v, v). Row stride 18 float2 =
    // 144B (16B multiple); explicit 16B alignment for the LDS.128 reads.
    __shared__ __align__(16) float2 sy[ROWS_PB][18];

    const int tid  = threadIdx.x;
    const int lane = tid & 31;
    const int wid  = tid >> 5;               // 8 warps -> 8 x 128 t = 1024 t
    const int r0   = blockIdx.x * ROWS_PB;
    const int tcol = wid * 128 + lane * 4;

    // ---- A slice into registers: 17 i x 2 f32x2 packs (68 regs), coalesced
    unsigned long long apk[2 * ROWS17];
#pragma unroll
    for (int i = 0; i < ROWS17; ++i) {
        float4 a4 = *reinterpret_cast<const float4*>(&g_A[i * SEQ + tcol]);
        apk[2 * i + 0] = pack2(a4.x, a4.y);
        apk[2 * i + 1] = pack2(a4.z, a4.w);
    }

    // ---- stage duplicated y for this block's rows; i==16 computes const
    for (int idx = tid; idx < ROWS_PB * ROWS17; idx += 256) {
        int r = idx / ROWS17;
        int i = idx - r * ROWS17;
        float v;
        if (i < AR) {
            v = y[(size_t)(r0 + r) * AR + i];
        } else {
            const float* ur = u + (size_t)(r0 + r) * UD;
            v = w[16 + UD];                  // bias w[31]
#pragma unroll
            for (int j = 0; j < UD; ++j)
                v = fmaf(ur[j], w[16 + j], v);
        }
        sy[r][i] = make_float2(v, v);
    }
    __syncthreads();

    // ---- stream rows
#pragma unroll 2
    for (int r = 0; r < ROWS_PB; ++r) {
        const ulonglong2* yp = reinterpret_cast<const ulonglong2*>(&sy[r][0]);
        unsigned long long acc0 = 0ull, acc1 = 0ull;
#pragma unroll
        for (int p = 0; p < 8; ++p) {        // i = 2p, 2p+1
            ulonglong2 yd = yp[p];           // LDS.128 broadcast: (dup_2p, dup_2p+1)
            acc0 = ffma2(apk[4 * p + 0], yd.x, acc0);
            acc1 = ffma2(apk[4 * p + 1], yd.x, acc1);
            acc0 = ffma2(apk[4 * p + 2], yd.y, acc0);
            acc1 = ffma2(apk[4 * p + 3], yd.y, acc1);
        }
        {                                    // i = 16 (const row)
            unsigned long long yd =
                *reinterpret_cast<const unsigned long long*>(&sy[r][16]);
            acc0 = ffma2(apk[32], yd, acc0);
            acc1 = ffma2(apk[33], yd, acc1);
        }
        F2U a0, a1; a0.u = acc0; a1.u = acc1;
        *reinterpret_cast<float4*>(out + (size_t)(r0 + r) * SEQ + tcol) =
            make_float4(a0.f.x, a0.f.y, a1.f.x, a1.f.y);
    }
}

extern "C" void kernel_launch(void* const* d_in, const int* in_sizes, int n_in,
                              void* d_out, int out_size) {
    const float* y = (const float*)d_in[0];   // [65536,16]
    const float* u = (const float*)d_in[1];   // [65536,15]
    const float* w = (const float*)d_in[2];   // [32]
    float* out = (float*)d_out;               // [65536,1024]

    arx_setup_kernel<<<1, 32>>>(w);
    arx_main_kernel<<<BATCH / ROWS_PB, 256>>>(y, u, w, out);
}